// round 12
// baseline (speedup 1.0000x reference)
#include <cuda_runtime.h>
#include <math.h>

#define B_  4
#define S_  2048
#define D_  1024
#define H_  16
#define HS_ 64
#define M_  (B_ * S_)      // 8192 rows (b,s)
#define N3_ (3 * D_)       // 3072 fused QKV output cols

// ---------------- scratch (static device globals; no allocation) -------------
__device__ float g_Wcat[D_ * N3_];                 // [k=1024][n=3072] Wq|Wk|Wv
__device__ float g_q[B_ * H_ * S_ * HS_];          // [b,h,s,e]
__device__ float g_k[B_ * H_ * S_ * HS_];
__device__ float g_v[B_ * H_ * S_ * HS_];
__device__ float g_attn[M_ * D_];                  // [b,s,d]

// ---------------- 1) repack weights [H,D,HS] -> [D, 3D] ----------------------
__global__ void repack_w(const float* __restrict__ Wq,
                         const float* __restrict__ Wk,
                         const float* __restrict__ Wv) {
    int idx = blockIdx.x * blockDim.x + threadIdx.x;
    if (idx >= D_ * N3_) return;
    int d   = idx / N3_;
    int n   = idx % N3_;
    int wch = n >> 10;
    int rem = n & 1023;
    int h   = rem >> 6;
    int e   = rem & 63;
    const float* W = (wch == 0) ? Wq : (wch == 1) ? Wk : Wv;
    g_Wcat[idx] = W[(h * D_ + d) * HS_ + e];
}

// ---------------- double-buffered 128x128x16 SGEMM core ----------------------
// 256 threads, 8x8 microtile. smem: As[2][16][128] + Bs[2][16][128] = 32KB.
__device__ __forceinline__ void sgemm_tile(
    const float* __restrict__ Aptr,    // top-left of this block's 128-row slab
    const float* __restrict__ Bptr,    // col-offset applied by caller
    int lda, int ldb, int K,
    float (&acc)[8][8], float* sm)
{
    float (*As)[16][128] = (float(*)[16][128])sm;
    float (*Bs)[16][128] = (float(*)[16][128])(sm + 2 * 16 * 128);

    int tid  = threadIdx.x;
    int aRow = tid >> 1;              // 0..127
    int aCol = (tid & 1) * 8;         // 0 or 8
    int bRow = tid >> 4;              // 0..15
    int bCol = (tid & 15) * 8;        // 0..120
    int tr   = (tid >> 4) * 8;
    int tc   = (tid & 15) * 8;

    // preload stage 0
    float4 pa0 = *(const float4*)(Aptr + (size_t)aRow * lda + aCol);
    float4 pa1 = *(const float4*)(Aptr + (size_t)aRow * lda + aCol + 4);
    float4 pb0 = *(const float4*)(Bptr + (size_t)bRow * ldb + bCol);
    float4 pb1 = *(const float4*)(Bptr + (size_t)bRow * ldb + bCol + 4);

    As[0][aCol + 0][aRow] = pa0.x;
    As[0][aCol + 1][aRow] = pa0.y;
    As[0][aCol + 2][aRow] = pa0.z;
    As[0][aCol + 3][aRow] = pa0.w;
    As[0][aCol + 4][aRow] = pa1.x;
    As[0][aCol + 5][aRow] = pa1.y;
    As[0][aCol + 6][aRow] = pa1.z;
    As[0][aCol + 7][aRow] = pa1.w;
    *(float4*)&Bs[0][bRow][bCol]     = pb0;
    *(float4*)&Bs[0][bRow][bCol + 4] = pb1;
    __syncthreads();

    int p = 0;
    for (int k0 = 0; k0 < K; k0 += 16) {
        bool more = (k0 + 16) < K;
        if (more) {
            const float* An = Aptr + (size_t)aRow * lda + k0 + 16;
            pa0 = *(const float4*)(An + aCol);
            pa1 = *(const float4*)(An + aCol + 4);
            const float* Bn = Bptr + (size_t)(k0 + 16 + bRow) * ldb;
            pb0 = *(const float4*)(Bn + bCol);
            pb1 = *(const float4*)(Bn + bCol + 4);
        }
#pragma unroll
        for (int k = 0; k < 16; k++) {
            float4 a0 = *(float4*)&As[p][k][tr];
            float4 a1 = *(float4*)&As[p][k][tr + 4];
            float4 b0 = *(float4*)&Bs[p][k][tc];
            float4 b1 = *(float4*)&Bs[p][k][tc + 4];
            float ra[8] = {a0.x, a0.y, a0.z, a0.w, a1.x, a1.y, a1.z, a1.w};
            float rb[8] = {b0.x, b0.y, b0.z, b0.w, b1.x, b1.y, b1.z, b1.w};
#pragma unroll
            for (int i = 0; i < 8; i++)
#pragma unroll
                for (int j = 0; j < 8; j++) acc[i][j] += ra[i] * rb[j];
        }
        if (more) {
            int q = p ^ 1;
            As[q][aCol + 0][aRow] = pa0.x;
            As[q][aCol + 1][aRow] = pa0.y;
            As[q][aCol + 2][aRow] = pa0.z;
            As[q][aCol + 3][aRow] = pa0.w;
            As[q][aCol + 4][aRow] = pa1.x;
            As[q][aCol + 5][aRow] = pa1.y;
            As[q][aCol + 6][aRow] = pa1.z;
            As[q][aCol + 7][aRow] = pa1.w;
            *(float4*)&Bs[q][bRow][bCol]     = pb0;
            *(float4*)&Bs[q][bRow][bCol + 4] = pb1;
            __syncthreads();
            p = q;
        }
    }
}

// ---------------- 2) fused QKV SGEMM ------------------------------------------
__global__ __launch_bounds__(256) void gemm_qkv(const float* __restrict__ x) {
    __shared__ float sm[2 * 16 * 128 * 2];
    int bm = blockIdx.y, bn = blockIdx.x;
    int tid = threadIdx.x;

    float acc[8][8];
#pragma unroll
    for (int i = 0; i < 8; i++)
#pragma unroll
        for (int j = 0; j < 8; j++) acc[i][j] = 0.f;

    sgemm_tile(x + (size_t)(bm * 128) * D_, g_Wcat + bn * 128, D_, N3_, D_, acc, sm);

    int tr = (tid >> 4) * 8, tc = (tid & 15) * 8;
    int mBase = bm * 128 + tr;
    int nBase = bn * 128 + tc;
#pragma unroll
    for (int i = 0; i < 8; i++) {
        int m = mBase + i;
        int b = m >> 11;
        int s = m & 2047;
#pragma unroll
        for (int j = 0; j < 8; j++) {
            int n   = nBase + j;
            int wch = n >> 10;
            int rem = n & 1023;
            int h   = rem >> 6;
            int e   = rem & 63;
            size_t off = (size_t)(((b * H_ + h) * S_) + s) * HS_ + e;
            float* dst = (wch == 0) ? g_q : (wch == 1) ? g_k : g_v;
            dst[off] = acc[i][j];
        }
    }
}

// ---------------- 4) output projection + bias ---------------------------------
__global__ __launch_bounds__(256) void gemm_out(const float* __restrict__ Wo,
                                                const float* __restrict__ bo,
                                                float* __restrict__ out) {
    __shared__ float sm[2 * 16 * 128 * 2];
    int bm = blockIdx.y, bn = blockIdx.x;
    int tid = threadIdx.x;

    float acc[8][8];
#pragma unroll
    for (int i = 0; i < 8; i++)
#pragma unroll
        for (int j = 0; j < 8; j++) acc[i][j] = 0.f;

    sgemm_tile(g_attn + (size_t)(bm * 128) * D_, Wo + bn * 128, D_, D_, D_, acc, sm);

    int tr = (tid >> 4) * 8, tc = (tid & 15) * 8;
    int mBase = bm * 128 + tr;
    int nBase = bn * 128 + tc;
#pragma unroll
    for (int i = 0; i < 8; i++) {
        float* row = out + (size_t)(mBase + i) * D_ + nBase;
#pragma unroll
        for (int j = 0; j < 8; j += 4) {
            float4 o;
            o.x = acc[i][j + 0] + bo[nBase + j + 0];
            o.y = acc[i][j + 1] + bo[nBase + j + 1];
            o.z = acc[i][j + 2] + bo[nBase + j + 2];
            o.w = acc[i][j + 3] + bo[nBase + j + 3];
            *(float4*)(row + j) = o;
        }
    }
}

// ---------------- 3) causal flash attention (double-buffered K/V) -------------
#define FP 68
#define FT (64 * FP)
__global__ __launch_bounds__(256) void flash_attn() {
    extern __shared__ float sm[];
    float (*Qt)[FP]    = (float(*)[FP])(sm);             // [e][r]
    float (*Kt0)[FP]   = (float(*)[FP])(sm + 1 * FT);    // [e][c] stage 0
    float (*Kt1)[FP]   = (float(*)[FP])(sm + 2 * FT);    // [e][c] stage 1
    float (*Vs0)[FP]   = (float(*)[FP])(sm + 3 * FT);    // [c][e] stage 0
    float (*Vs1)[FP]   = (float(*)[FP])(sm + 4 * FT);    // [c][e] stage 1
    float (*Pt)[FP]    = (float(*)[FP])(sm + 5 * FT);    // [c][r]

    int qb = blockIdx.x;
    int bh = blockIdx.y;
    int b  = bh >> 4;
    int h  = bh & 15;

    const float* Q = g_q + (size_t)bh * S_ * HS_;
    const float* K = g_k + (size_t)bh * S_ * HS_;
    const float* V = g_v + (size_t)bh * S_ * HS_;

    int tid = threadIdx.x;
    int ty = tid >> 4, tx = tid & 15;
    int r0 = ty * 4, c0 = tx * 4;

    const float qk_scale = 0.125f;

    // load Q tile (scaled, transposed) + stage-0 K/V tiles
    for (int idx = tid; idx < 64 * 64; idx += 256) {
        int r = idx >> 6, e = idx & 63;
        Qt[e][r] = Q[(size_t)(qb * 64 + r) * HS_ + e] * qk_scale;
    }
#pragma unroll
    for (int i = 0; i < 4; i++) {
        int idx4 = tid + i * 256;            // float4 index in 64x64 tile
        int c  = idx4 >> 4;
        int e4 = (idx4 & 15) * 4;
        float4 kv = *(const float4*)(K + (size_t)c * HS_ + e4);
        float4 vv = *(const float4*)(V + (size_t)c * HS_ + e4);
        Kt0[e4 + 0][c] = kv.x;
        Kt0[e4 + 1][c] = kv.y;
        Kt0[e4 + 2][c] = kv.z;
        Kt0[e4 + 3][c] = kv.w;
        *(float4*)&Vs0[c][e4] = vv;
    }
    __syncthreads();

    float m_i[4], l_i[4], acc[4][4];
#pragma unroll
    for (int i = 0; i < 4; i++) {
        m_i[i] = -INFINITY; l_i[i] = 0.f;
#pragma unroll
        for (int j = 0; j < 4; j++) acc[i][j] = 0.f;
    }

    int p = 0;
    for (int kb = 0; kb <= qb; kb++) {
        bool more = (kb < qb);
        float4 rk[4], rv[4];
        if (more) {
            const float* Kn = K + (size_t)(kb + 1) * 64 * HS_;
            const float* Vn = V + (size_t)(kb + 1) * 64 * HS_;
#pragma unroll
            for (int i = 0; i < 4; i++) {
                int idx4 = tid + i * 256;
                rk[i] = *(const float4*)(Kn + idx4 * 4);
                rv[i] = *(const float4*)(Vn + idx4 * 4);
            }
        }

        float (*Ktp)[FP] = p ? Kt1 : Kt0;
        float (*Vsp)[FP] = p ? Vs1 : Vs0;

        // scores S = Q K^T
        float s[4][4];
#pragma unroll
        for (int i = 0; i < 4; i++)
#pragma unroll
            for (int j = 0; j < 4; j++) s[i][j] = 0.f;
#pragma unroll 8
        for (int e = 0; e < 64; e++) {
            float4 qv = *(float4*)&Qt[e][r0];
            float4 kv = *(float4*)&Ktp[e][c0];
            float ra[4] = {qv.x, qv.y, qv.z, qv.w};
            float rb[4] = {kv.x, kv.y, kv.z, kv.w};
#pragma unroll
            for (int i = 0; i < 4; i++)
#pragma unroll
                for (int j = 0; j < 4; j++) s[i][j] += ra[i] * rb[j];
        }

        if (kb == qb) {
#pragma unroll
            for (int i = 0; i < 4; i++)
#pragma unroll
                for (int j = 0; j < 4; j++)
                    if (c0 + j > r0 + i) s[i][j] = -INFINITY;
        }

        // online softmax
#pragma unroll
        for (int i = 0; i < 4; i++) {
            float mrow = fmaxf(fmaxf(s[i][0], s[i][1]), fmaxf(s[i][2], s[i][3]));
#pragma unroll
            for (int off = 8; off > 0; off >>= 1)
                mrow = fmaxf(mrow, __shfl_xor_sync(0xffffffffu, mrow, off, 16));
            float m_new = fmaxf(m_i[i], mrow);
            float alpha = __expf(m_i[i] - m_new);
            float rsum = 0.f;
#pragma unroll
            for (int j = 0; j < 4; j++) {
                float pj = __expf(s[i][j] - m_new);
                s[i][j] = pj;
                rsum += pj;
            }
#pragma unroll
            for (int off = 8; off > 0; off >>= 1)
                rsum += __shfl_xor_sync(0xffffffffu, rsum, off, 16);
            l_i[i] = l_i[i] * alpha + rsum;
            m_i[i] = m_new;
#pragma unroll
            for (int j = 0; j < 4; j++) acc[i][j] *= alpha;
        }

        __syncthreads();   // prev PV done with Pt; stage p^1 free

        // stage P (transposed); park next K/V tile in stage p^1
#pragma unroll
        for (int i = 0; i < 4; i++)
#pragma unroll
            for (int j = 0; j < 4; j++) Pt[c0 + j][r0 + i] = s[i][j];

        if (more) {
            float (*Ktn)[FP] = p ? Kt0 : Kt1;
            float (*Vsn)[FP] = p ? Vs0 : Vs1;
#pragma unroll
            for (int i = 0; i < 4; i++) {
                int idx4 = tid + i * 256;
                int c  = idx4 >> 4;
                int e4 = (idx4 & 15) * 4;
                Ktn[e4 + 0][c] = rk[i].x;
                Ktn[e4 + 1][c] = rk[i].y;
                Ktn[e4 + 2][c] = rk[i].z;
                Ktn[e4 + 3][c] = rk[i].w;
                *(float4*)&Vsn[c][e4] = rv[i];
            }
        }
        __syncthreads();

        // O += P @ V
#pragma unroll 8
        for (int c = 0; c < 64; c++) {
            float4 pv = *(float4*)&Pt[c][r0];
            float4 vv = *(float4*)&Vsp[c][c0];
            float ra[4] = {pv.x, pv.y, pv.z, pv.w};
            float rb[4] = {vv.x, vv.y, vv.z, vv.w};
#pragma unroll
            for (int i = 0; i < 4; i++)
#pragma unroll
                for (int j = 0; j < 4; j++) acc[i][j] += ra[i] * rb[j];
        }
        p ^= 1;
    }

    // write O in [b,s,d] layout
#pragma unroll
    for (int i = 0; i < 4; i++) {
        float inv_l = 1.f / l_i[i];
        int srow = qb * 64 + r0 + i;
        float4 o;
        o.x = acc[i][0] * inv_l;
        o.y = acc[i][1] * inv_l;
        o.z = acc[i][2] * inv_l;
        o.w = acc[i][3] * inv_l;
        *(float4*)&g_attn[(size_t)(b * S_ + srow) * D_ + h * HS_ + c0] = o;
    }
}

// ---------------- launch ------------------------------------------------------
extern "C" void kernel_launch(void* const* d_in, const int* in_sizes, int n_in,
                              void* d_out, int out_size) {
    const float* x  = (const float*)d_in[0];
    const float* Wq = (const float*)d_in[1];
    const float* Wk = (const float*)d_in[2];
    const float* Wv = (const float*)d_in[3];
    const float* Wo = (const float*)d_in[4];
    const float* bo = (const float*)d_in[5];
    float* out = (float*)d_out;

    {
        int total = D_ * N3_;
        repack_w<<<(total + 255) / 256, 256>>>(Wq, Wk, Wv);
    }
    {
        dim3 grid(N3_ / 128, M_ / 128);
        gemm_qkv<<<grid, 256>>>(x);
    }
    {
        int smem = 6 * FT * sizeof(float);   // 104448 B
        static bool attr_set = false;
        if (!attr_set) {
            cudaFuncSetAttribute(flash_attn,
                                 cudaFuncAttributeMaxDynamicSharedMemorySize, smem);
            attr_set = true;
        }
        dim3 grid(S_ / 64, B_ * H_);
        flash_attn<<<grid, 256, smem>>>();
    }
    {
        dim3 grid(D_ / 128, M_ / 128);
        gemm_out<<<grid, 256>>>(Wo, bo, out);
    }
}

// round 13
// speedup vs baseline: 1.0035x; 1.0035x over previous
#include <cuda_runtime.h>
#include <math.h>

#define B_  4
#define S_  2048
#define D_  1024
#define H_  16
#define HS_ 64
#define M_  (B_ * S_)      // 8192 rows (b,s)
#define N3_ (3 * D_)       // 3072 fused QKV output cols

// ---------------- scratch (static device globals; no allocation) -------------
__device__ float g_Wcat[D_ * N3_];                 // [k=1024][n=3072] Wq|Wk|Wv
__device__ float g_q[B_ * H_ * S_ * HS_];          // [b,h,s,e]
__device__ float g_k[B_ * H_ * S_ * HS_];
__device__ float g_v[B_ * H_ * S_ * HS_];
__device__ float g_attn[M_ * D_];                  // [b,s,d]

// ---------------- 1) repack weights [H,D,HS] -> [D, 3D] ----------------------
__global__ void repack_w(const float* __restrict__ Wq,
                         const float* __restrict__ Wk,
                         const float* __restrict__ Wv) {
    int idx = blockIdx.x * blockDim.x + threadIdx.x;
    if (idx >= D_ * N3_) return;
    int d   = idx / N3_;
    int n   = idx % N3_;
    int wch = n >> 10;
    int rem = n & 1023;
    int h   = rem >> 6;
    int e   = rem & 63;
    const float* W = (wch == 0) ? Wq : (wch == 1) ? Wk : Wv;
    g_Wcat[idx] = W[(h * D_ + d) * HS_ + e];
}

// ---------------- double-buffered 128x128x16 SGEMM core ----------------------
// 256 threads, 8x8 microtile. smem: As[2][16][128] + Bs[2][16][128] = 32KB.
__device__ __forceinline__ void sgemm_tile(
    const float* __restrict__ Aptr,    // top-left of this block's 128-row slab
    const float* __restrict__ Bptr,    // col-offset applied by caller
    int lda, int ldb, int K,
    float (&acc)[8][8], float* sm)
{
    float (*As)[16][128] = (float(*)[16][128])sm;
    float (*Bs)[16][128] = (float(*)[16][128])(sm + 2 * 16 * 128);

    int tid  = threadIdx.x;
    int aRow = tid >> 1;              // 0..127
    int aCol = (tid & 1) * 8;         // 0 or 8
    int bRow = tid >> 4;              // 0..15
    int bCol = (tid & 15) * 8;        // 0..120
    int tr   = (tid >> 4) * 8;
    int tc   = (tid & 15) * 8;

    // preload stage 0
    float4 pa0 = *(const float4*)(Aptr + (size_t)aRow * lda + aCol);
    float4 pa1 = *(const float4*)(Aptr + (size_t)aRow * lda + aCol + 4);
    float4 pb0 = *(const float4*)(Bptr + (size_t)bRow * ldb + bCol);
    float4 pb1 = *(const float4*)(Bptr + (size_t)bRow * ldb + bCol + 4);

    As[0][aCol + 0][aRow] = pa0.x;
    As[0][aCol + 1][aRow] = pa0.y;
    As[0][aCol + 2][aRow] = pa0.z;
    As[0][aCol + 3][aRow] = pa0.w;
    As[0][aCol + 4][aRow] = pa1.x;
    As[0][aCol + 5][aRow] = pa1.y;
    As[0][aCol + 6][aRow] = pa1.z;
    As[0][aCol + 7][aRow] = pa1.w;
    *(float4*)&Bs[0][bRow][bCol]     = pb0;
    *(float4*)&Bs[0][bRow][bCol + 4] = pb1;
    __syncthreads();

    int p = 0;
    for (int k0 = 0; k0 < K; k0 += 16) {
        bool more = (k0 + 16) < K;
        if (more) {
            const float* An = Aptr + (size_t)aRow * lda + k0 + 16;
            pa0 = *(const float4*)(An + aCol);
            pa1 = *(const float4*)(An + aCol + 4);
            const float* Bn = Bptr + (size_t)(k0 + 16 + bRow) * ldb;
            pb0 = *(const float4*)(Bn + bCol);
            pb1 = *(const float4*)(Bn + bCol + 4);
        }
#pragma unroll
        for (int k = 0; k < 16; k++) {
            float4 a0 = *(float4*)&As[p][k][tr];
            float4 a1 = *(float4*)&As[p][k][tr + 4];
            float4 b0 = *(float4*)&Bs[p][k][tc];
            float4 b1 = *(float4*)&Bs[p][k][tc + 4];
            float ra[8] = {a0.x, a0.y, a0.z, a0.w, a1.x, a1.y, a1.z, a1.w};
            float rb[8] = {b0.x, b0.y, b0.z, b0.w, b1.x, b1.y, b1.z, b1.w};
#pragma unroll
            for (int i = 0; i < 8; i++)
#pragma unroll
                for (int j = 0; j < 8; j++) acc[i][j] += ra[i] * rb[j];
        }
        if (more) {
            int q = p ^ 1;
            As[q][aCol + 0][aRow] = pa0.x;
            As[q][aCol + 1][aRow] = pa0.y;
            As[q][aCol + 2][aRow] = pa0.z;
            As[q][aCol + 3][aRow] = pa0.w;
            As[q][aCol + 4][aRow] = pa1.x;
            As[q][aCol + 5][aRow] = pa1.y;
            As[q][aCol + 6][aRow] = pa1.z;
            As[q][aCol + 7][aRow] = pa1.w;
            *(float4*)&Bs[q][bRow][bCol]     = pb0;
            *(float4*)&Bs[q][bRow][bCol + 4] = pb1;
            __syncthreads();
            p = q;
        }
    }
}

// ---------------- 2) fused QKV SGEMM ------------------------------------------
__global__ __launch_bounds__(256) void gemm_qkv(const float* __restrict__ x) {
    __shared__ float sm[2 * 16 * 128 * 2];
    int bm = blockIdx.y, bn = blockIdx.x;
    int tid = threadIdx.x;

    float acc[8][8];
#pragma unroll
    for (int i = 0; i < 8; i++)
#pragma unroll
        for (int j = 0; j < 8; j++) acc[i][j] = 0.f;

    sgemm_tile(x + (size_t)(bm * 128) * D_, g_Wcat + bn * 128, D_, N3_, D_, acc, sm);

    int tr = (tid >> 4) * 8, tc = (tid & 15) * 8;
    int mBase = bm * 128 + tr;
    int nBase = bn * 128 + tc;
#pragma unroll
    for (int i = 0; i < 8; i++) {
        int m = mBase + i;
        int b = m >> 11;
        int s = m & 2047;
#pragma unroll
        for (int j = 0; j < 8; j++) {
            int n   = nBase + j;
            int wch = n >> 10;
            int rem = n & 1023;
            int h   = rem >> 6;
            int e   = rem & 63;
            size_t off = (size_t)(((b * H_ + h) * S_) + s) * HS_ + e;
            float* dst = (wch == 0) ? g_q : (wch == 1) ? g_k : g_v;
            dst[off] = acc[i][j];
        }
    }
}

// ---------------- 4) output projection + bias ---------------------------------
__global__ __launch_bounds__(256) void gemm_out(const float* __restrict__ Wo,
                                                const float* __restrict__ bo,
                                                float* __restrict__ out) {
    __shared__ float sm[2 * 16 * 128 * 2];
    int bm = blockIdx.y, bn = blockIdx.x;
    int tid = threadIdx.x;

    float acc[8][8];
#pragma unroll
    for (int i = 0; i < 8; i++)
#pragma unroll
        for (int j = 0; j < 8; j++) acc[i][j] = 0.f;

    sgemm_tile(g_attn + (size_t)(bm * 128) * D_, Wo + bn * 128, D_, D_, D_, acc, sm);

    int tr = (tid >> 4) * 8, tc = (tid & 15) * 8;
    int mBase = bm * 128 + tr;
    int nBase = bn * 128 + tc;
#pragma unroll
    for (int i = 0; i < 8; i++) {
        float* row = out + (size_t)(mBase + i) * D_ + nBase;
#pragma unroll
        for (int j = 0; j < 8; j += 4) {
            float4 o;
            o.x = acc[i][j + 0] + bo[nBase + j + 0];
            o.y = acc[i][j + 1] + bo[nBase + j + 1];
            o.z = acc[i][j + 2] + bo[nBase + j + 2];
            o.w = acc[i][j + 3] + bo[nBase + j + 3];
            *(float4*)(row + j) = o;
        }
    }
}

// ---------------- 3) causal flash attention (double-buffered K/V) -------------
#define FP 68
#define FT (64 * FP)
__global__ __launch_bounds__(256) void flash_attn() {
    extern __shared__ float sm[];
    float (*Qt)[FP]    = (float(*)[FP])(sm);             // [e][r]
    float (*Kt0)[FP]   = (float(*)[FP])(sm + 1 * FT);    // [e][c] stage 0
    float (*Kt1)[FP]   = (float(*)[FP])(sm + 2 * FT);    // [e][c] stage 1
    float (*Vs0)[FP]   = (float(*)[FP])(sm + 3 * FT);    // [c][e] stage 0
    float (*Vs1)[FP]   = (float(*)[FP])(sm + 4 * FT);    // [c][e] stage 1
    float (*Pt)[FP]    = (float(*)[FP])(sm + 5 * FT);    // [c][r]

    int qb = blockIdx.x;
    int bh = blockIdx.y;
    int b  = bh >> 4;
    int h  = bh & 15;

    const float* Q = g_q + (size_t)bh * S_ * HS_;
    const float* K = g_k + (size_t)bh * S_ * HS_;
    const float* V = g_v + (size_t)bh * S_ * HS_;

    int tid = threadIdx.x;
    int ty = tid >> 4, tx = tid & 15;
    int r0 = ty * 4, c0 = tx * 4;

    const float qk_scale = 0.125f;

    // load Q tile (scaled, transposed) + stage-0 K/V tiles
    for (int idx = tid; idx < 64 * 64; idx += 256) {
        int r = idx >> 6, e = idx & 63;
        Qt[e][r] = Q[(size_t)(qb * 64 + r) * HS_ + e] * qk_scale;
    }
#pragma unroll
    for (int i = 0; i < 4; i++) {
        int idx4 = tid + i * 256;            // float4 index in 64x64 tile
        int c  = idx4 >> 4;
        int e4 = (idx4 & 15) * 4;
        float4 kv = *(const float4*)(K + (size_t)c * HS_ + e4);
        float4 vv = *(const float4*)(V + (size_t)c * HS_ + e4);
        Kt0[e4 + 0][c] = kv.x;
        Kt0[e4 + 1][c] = kv.y;
        Kt0[e4 + 2][c] = kv.z;
        Kt0[e4 + 3][c] = kv.w;
        *(float4*)&Vs0[c][e4] = vv;
    }
    __syncthreads();

    float m_i[4], l_i[4], acc[4][4];
#pragma unroll
    for (int i = 0; i < 4; i++) {
        m_i[i] = -INFINITY; l_i[i] = 0.f;
#pragma unroll
        for (int j = 0; j < 4; j++) acc[i][j] = 0.f;
    }

    int p = 0;
    for (int kb = 0; kb <= qb; kb++) {
        bool more = (kb < qb);
        float4 rk[4], rv[4];
        if (more) {
            const float* Kn = K + (size_t)(kb + 1) * 64 * HS_;
            const float* Vn = V + (size_t)(kb + 1) * 64 * HS_;
#pragma unroll
            for (int i = 0; i < 4; i++) {
                int idx4 = tid + i * 256;
                rk[i] = *(const float4*)(Kn + idx4 * 4);
                rv[i] = *(const float4*)(Vn + idx4 * 4);
            }
        }

        float (*Ktp)[FP] = p ? Kt1 : Kt0;
        float (*Vsp)[FP] = p ? Vs1 : Vs0;

        // scores S = Q K^T
        float s[4][4];
#pragma unroll
        for (int i = 0; i < 4; i++)
#pragma unroll
            for (int j = 0; j < 4; j++) s[i][j] = 0.f;
#pragma unroll 8
        for (int e = 0; e < 64; e++) {
            float4 qv = *(float4*)&Qt[e][r0];
            float4 kv = *(float4*)&Ktp[e][c0];
            float ra[4] = {qv.x, qv.y, qv.z, qv.w};
            float rb[4] = {kv.x, kv.y, kv.z, kv.w};
#pragma unroll
            for (int i = 0; i < 4; i++)
#pragma unroll
                for (int j = 0; j < 4; j++) s[i][j] += ra[i] * rb[j];
        }

        if (kb == qb) {
#pragma unroll
            for (int i = 0; i < 4; i++)
#pragma unroll
                for (int j = 0; j < 4; j++)
                    if (c0 + j > r0 + i) s[i][j] = -INFINITY;
        }

        // online softmax
#pragma unroll
        for (int i = 0; i < 4; i++) {
            float mrow = fmaxf(fmaxf(s[i][0], s[i][1]), fmaxf(s[i][2], s[i][3]));
#pragma unroll
            for (int off = 8; off > 0; off >>= 1)
                mrow = fmaxf(mrow, __shfl_xor_sync(0xffffffffu, mrow, off, 16));
            float m_new = fmaxf(m_i[i], mrow);
            float alpha = __expf(m_i[i] - m_new);
            float rsum = 0.f;
#pragma unroll
            for (int j = 0; j < 4; j++) {
                float pj = __expf(s[i][j] - m_new);
                s[i][j] = pj;
                rsum += pj;
            }
#pragma unroll
            for (int off = 8; off > 0; off >>= 1)
                rsum += __shfl_xor_sync(0xffffffffu, rsum, off, 16);
            l_i[i] = l_i[i] * alpha + rsum;
            m_i[i] = m_new;
#pragma unroll
            for (int j = 0; j < 4; j++) acc[i][j] *= alpha;
        }

        __syncthreads();   // prev PV done with Pt; stage p^1 free

        // stage P (transposed); park next K/V tile in stage p^1
#pragma unroll
        for (int i = 0; i < 4; i++)
#pragma unroll
            for (int j = 0; j < 4; j++) Pt[c0 + j][r0 + i] = s[i][j];

        if (more) {
            float (*Ktn)[FP] = p ? Kt0 : Kt1;
            float (*Vsn)[FP] = p ? Vs0 : Vs1;
#pragma unroll
            for (int i = 0; i < 4; i++) {
                int idx4 = tid + i * 256;
                int c  = idx4 >> 4;
                int e4 = (idx4 & 15) * 4;
                Ktn[e4 + 0][c] = rk[i].x;
                Ktn[e4 + 1][c] = rk[i].y;
                Ktn[e4 + 2][c] = rk[i].z;
                Ktn[e4 + 3][c] = rk[i].w;
                *(float4*)&Vsn[c][e4] = rv[i];
            }
        }
        __syncthreads();

        // O += P @ V
#pragma unroll 8
        for (int c = 0; c < 64; c++) {
            float4 pv = *(float4*)&Pt[c][r0];
            float4 vv = *(float4*)&Vsp[c][c0];
            float ra[4] = {pv.x, pv.y, pv.z, pv.w};
            float rb[4] = {vv.x, vv.y, vv.z, vv.w};
#pragma unroll
            for (int i = 0; i < 4; i++)
#pragma unroll
                for (int j = 0; j < 4; j++) acc[i][j] += ra[i] * rb[j];
        }
        p ^= 1;
    }

    // write O in [b,s,d] layout
#pragma unroll
    for (int i = 0; i < 4; i++) {
        float inv_l = 1.f / l_i[i];
        int srow = qb * 64 + r0 + i;
        float4 o;
        o.x = acc[i][0] * inv_l;
        o.y = acc[i][1] * inv_l;
        o.z = acc[i][2] * inv_l;
        o.w = acc[i][3] * inv_l;
        *(float4*)&g_attn[(size_t)(b * S_ + srow) * D_ + h * HS_ + c0] = o;
    }
}

// ---------------- launch ------------------------------------------------------
extern "C" void kernel_launch(void* const* d_in, const int* in_sizes, int n_in,
                              void* d_out, int out_size) {
    const float* x  = (const float*)d_in[0];
    const float* Wq = (const float*)d_in[1];
    const float* Wk = (const float*)d_in[2];
    const float* Wv = (const float*)d_in[3];
    const float* Wo = (const float*)d_in[4];
    const float* bo = (const float*)d_in[5];
    float* out = (float*)d_out;

    {
        int total = D_ * N3_;
        repack_w<<<(total + 255) / 256, 256>>>(Wq, Wk, Wv);
    }
    {
        dim3 grid(N3_ / 128, M_ / 128);
        gemm_qkv<<<grid, 256>>>(x);
    }
    {
        int smem = 6 * FT * sizeof(float);   // 104448 B
        static bool attr_set = false;
        if (!attr_set) {
            cudaFuncSetAttribute(flash_attn,
                                 cudaFuncAttributeMaxDynamicSharedMemorySize, smem);
            attr_set = true;
        }
        dim3 grid(S_ / 64, B_ * H_);
        flash_attn<<<grid, 256, smem>>>();
    }
    {
        dim3 grid(D_ / 128, M_ / 128);
        gemm_out<<<grid, 256>>>(Wo, bo, out);
    }
}

// round 14
// speedup vs baseline: 1.0046x; 1.0011x over previous
#include <cuda_runtime.h>
#include <math.h>

#define B_  4
#define S_  2048
#define D_  1024
#define H_  16
#define HS_ 64
#define M_  (B_ * S_)      // 8192 rows (b,s)
#define N3_ (3 * D_)       // 3072 fused QKV output cols

// ---------------- scratch (static device globals; no allocation) -------------
__device__ float g_Wcat[D_ * N3_];                 // [k=1024][n=3072] Wq|Wk|Wv
__device__ float g_q[B_ * H_ * S_ * HS_];          // [b,h,s,e]
__device__ float g_k[B_ * H_ * S_ * HS_];
__device__ float g_v[B_ * H_ * S_ * HS_];
__device__ float g_attn[M_ * D_];                  // [b,s,d]

// ---------------- 1) repack weights [H,D,HS] -> [D, 3D] ----------------------
__global__ void repack_w(const float* __restrict__ Wq,
                         const float* __restrict__ Wk,
                         const float* __restrict__ Wv) {
    int idx = blockIdx.x * blockDim.x + threadIdx.x;
    if (idx >= D_ * N3_) return;
    int d   = idx / N3_;
    int n   = idx % N3_;
    int wch = n >> 10;
    int rem = n & 1023;
    int h   = rem >> 6;
    int e   = rem & 63;
    const float* W = (wch == 0) ? Wq : (wch == 1) ? Wk : Wv;
    g_Wcat[idx] = W[(h * D_ + d) * HS_ + e];
}

// ---------------- double-buffered 128x128x16 SGEMM core ----------------------
// 256 threads, 8x8 microtile. smem: As[2][16][128] + Bs[2][16][128] = 32KB.
__device__ __forceinline__ void sgemm_tile(
    const float* __restrict__ Aptr,    // top-left of this block's 128-row slab
    const float* __restrict__ Bptr,    // col-offset applied by caller
    int lda, int ldb, int K,
    float (&acc)[8][8], float* sm)
{
    float (*As)[16][128] = (float(*)[16][128])sm;
    float (*Bs)[16][128] = (float(*)[16][128])(sm + 2 * 16 * 128);

    int tid  = threadIdx.x;
    int aRow = tid >> 1;              // 0..127
    int aCol = (tid & 1) * 8;         // 0 or 8
    int bRow = tid >> 4;              // 0..15
    int bCol = (tid & 15) * 8;        // 0..120
    int tr   = (tid >> 4) * 8;
    int tc   = (tid & 15) * 8;

    // preload stage 0
    float4 pa0 = *(const float4*)(Aptr + (size_t)aRow * lda + aCol);
    float4 pa1 = *(const float4*)(Aptr + (size_t)aRow * lda + aCol + 4);
    float4 pb0 = *(const float4*)(Bptr + (size_t)bRow * ldb + bCol);
    float4 pb1 = *(const float4*)(Bptr + (size_t)bRow * ldb + bCol + 4);

    As[0][aCol + 0][aRow] = pa0.x;
    As[0][aCol + 1][aRow] = pa0.y;
    As[0][aCol + 2][aRow] = pa0.z;
    As[0][aCol + 3][aRow] = pa0.w;
    As[0][aCol + 4][aRow] = pa1.x;
    As[0][aCol + 5][aRow] = pa1.y;
    As[0][aCol + 6][aRow] = pa1.z;
    As[0][aCol + 7][aRow] = pa1.w;
    *(float4*)&Bs[0][bRow][bCol]     = pb0;
    *(float4*)&Bs[0][bRow][bCol + 4] = pb1;
    __syncthreads();

    int p = 0;
    for (int k0 = 0; k0 < K; k0 += 16) {
        bool more = (k0 + 16) < K;
        if (more) {
            const float* An = Aptr + (size_t)aRow * lda + k0 + 16;
            pa0 = *(const float4*)(An + aCol);
            pa1 = *(const float4*)(An + aCol + 4);
            const float* Bn = Bptr + (size_t)(k0 + 16 + bRow) * ldb;
            pb0 = *(const float4*)(Bn + bCol);
            pb1 = *(const float4*)(Bn + bCol + 4);
        }
#pragma unroll
        for (int k = 0; k < 16; k++) {
            float4 a0 = *(float4*)&As[p][k][tr];
            float4 a1 = *(float4*)&As[p][k][tr + 4];
            float4 b0 = *(float4*)&Bs[p][k][tc];
            float4 b1 = *(float4*)&Bs[p][k][tc + 4];
            float ra[8] = {a0.x, a0.y, a0.z, a0.w, a1.x, a1.y, a1.z, a1.w};
            float rb[8] = {b0.x, b0.y, b0.z, b0.w, b1.x, b1.y, b1.z, b1.w};
#pragma unroll
            for (int i = 0; i < 8; i++)
#pragma unroll
                for (int j = 0; j < 8; j++) acc[i][j] += ra[i] * rb[j];
        }
        if (more) {
            int q = p ^ 1;
            As[q][aCol + 0][aRow] = pa0.x;
            As[q][aCol + 1][aRow] = pa0.y;
            As[q][aCol + 2][aRow] = pa0.z;
            As[q][aCol + 3][aRow] = pa0.w;
            As[q][aCol + 4][aRow] = pa1.x;
            As[q][aCol + 5][aRow] = pa1.y;
            As[q][aCol + 6][aRow] = pa1.z;
            As[q][aCol + 7][aRow] = pa1.w;
            *(float4*)&Bs[q][bRow][bCol]     = pb0;
            *(float4*)&Bs[q][bRow][bCol + 4] = pb1;
            __syncthreads();
            p = q;
        }
    }
}

// ---------------- 2) fused QKV SGEMM ------------------------------------------
__global__ __launch_bounds__(256) void gemm_qkv(const float* __restrict__ x) {
    __shared__ float sm[2 * 16 * 128 * 2];
    int bm = blockIdx.y, bn = blockIdx.x;
    int tid = threadIdx.x;

    float acc[8][8];
#pragma unroll
    for (int i = 0; i < 8; i++)
#pragma unroll
        for (int j = 0; j < 8; j++) acc[i][j] = 0.f;

    sgemm_tile(x + (size_t)(bm * 128) * D_, g_Wcat + bn * 128, D_, N3_, D_, acc, sm);

    int tr = (tid >> 4) * 8, tc = (tid & 15) * 8;
    int mBase = bm * 128 + tr;
    int nBase = bn * 128 + tc;
#pragma unroll
    for (int i = 0; i < 8; i++) {
        int m = mBase + i;
        int b = m >> 11;
        int s = m & 2047;
#pragma unroll
        for (int j = 0; j < 8; j++) {
            int n   = nBase + j;
            int wch = n >> 10;
            int rem = n & 1023;
            int h   = rem >> 6;
            int e   = rem & 63;
            size_t off = (size_t)(((b * H_ + h) * S_) + s) * HS_ + e;
            float* dst = (wch == 0) ? g_q : (wch == 1) ? g_k : g_v;
            dst[off] = acc[i][j];
        }
    }
}

// ---------------- 4) output projection + bias ---------------------------------
__global__ __launch_bounds__(256) void gemm_out(const float* __restrict__ Wo,
                                                const float* __restrict__ bo,
                                                float* __restrict__ out) {
    __shared__ float sm[2 * 16 * 128 * 2];
    int bm = blockIdx.y, bn = blockIdx.x;
    int tid = threadIdx.x;

    float acc[8][8];
#pragma unroll
    for (int i = 0; i < 8; i++)
#pragma unroll
        for (int j = 0; j < 8; j++) acc[i][j] = 0.f;

    sgemm_tile(g_attn + (size_t)(bm * 128) * D_, Wo + bn * 128, D_, D_, D_, acc, sm);

    int tr = (tid >> 4) * 8, tc = (tid & 15) * 8;
    int mBase = bm * 128 + tr;
    int nBase = bn * 128 + tc;
#pragma unroll
    for (int i = 0; i < 8; i++) {
        float* row = out + (size_t)(mBase + i) * D_ + nBase;
#pragma unroll
        for (int j = 0; j < 8; j += 4) {
            float4 o;
            o.x = acc[i][j + 0] + bo[nBase + j + 0];
            o.y = acc[i][j + 1] + bo[nBase + j + 1];
            o.z = acc[i][j + 2] + bo[nBase + j + 2];
            o.w = acc[i][j + 3] + bo[nBase + j + 3];
            *(float4*)(row + j) = o;
        }
    }
}

// ---------------- 3) causal flash attention (double-buffered K/V) -------------
#define FP 68
#define FT (64 * FP)
__global__ __launch_bounds__(256) void flash_attn() {
    extern __shared__ float sm[];
    float (*Qt)[FP]    = (float(*)[FP])(sm);             // [e][r]
    float (*Kt0)[FP]   = (float(*)[FP])(sm + 1 * FT);    // [e][c] stage 0
    float (*Kt1)[FP]   = (float(*)[FP])(sm + 2 * FT);    // [e][c] stage 1
    float (*Vs0)[FP]   = (float(*)[FP])(sm + 3 * FT);    // [c][e] stage 0
    float (*Vs1)[FP]   = (float(*)[FP])(sm + 4 * FT);    // [c][e] stage 1
    float (*Pt)[FP]    = (float(*)[FP])(sm + 5 * FT);    // [c][r]

    int qb = blockIdx.x;
    int bh = blockIdx.y;
    int b  = bh >> 4;
    int h  = bh & 15;

    const float* Q = g_q + (size_t)bh * S_ * HS_;
    const float* K = g_k + (size_t)bh * S_ * HS_;
    const float* V = g_v + (size_t)bh * S_ * HS_;

    int tid = threadIdx.x;
    int ty = tid >> 4, tx = tid & 15;
    int r0 = ty * 4, c0 = tx * 4;

    const float qk_scale = 0.125f;

    // load Q tile (scaled, transposed) + stage-0 K/V tiles
    for (int idx = tid; idx < 64 * 64; idx += 256) {
        int r = idx >> 6, e = idx & 63;
        Qt[e][r] = Q[(size_t)(qb * 64 + r) * HS_ + e] * qk_scale;
    }
#pragma unroll
    for (int i = 0; i < 4; i++) {
        int idx4 = tid + i * 256;            // float4 index in 64x64 tile
        int c  = idx4 >> 4;
        int e4 = (idx4 & 15) * 4;
        float4 kv = *(const float4*)(K + (size_t)c * HS_ + e4);
        float4 vv = *(const float4*)(V + (size_t)c * HS_ + e4);
        Kt0[e4 + 0][c] = kv.x;
        Kt0[e4 + 1][c] = kv.y;
        Kt0[e4 + 2][c] = kv.z;
        Kt0[e4 + 3][c] = kv.w;
        *(float4*)&Vs0[c][e4] = vv;
    }
    __syncthreads();

    float m_i[4], l_i[4], acc[4][4];
#pragma unroll
    for (int i = 0; i < 4; i++) {
        m_i[i] = -INFINITY; l_i[i] = 0.f;
#pragma unroll
        for (int j = 0; j < 4; j++) acc[i][j] = 0.f;
    }

    int p = 0;
    for (int kb = 0; kb <= qb; kb++) {
        bool more = (kb < qb);
        float4 rk[4], rv[4];
        if (more) {
            const float* Kn = K + (size_t)(kb + 1) * 64 * HS_;
            const float* Vn = V + (size_t)(kb + 1) * 64 * HS_;
#pragma unroll
            for (int i = 0; i < 4; i++) {
                int idx4 = tid + i * 256;
                rk[i] = *(const float4*)(Kn + idx4 * 4);
                rv[i] = *(const float4*)(Vn + idx4 * 4);
            }
        }

        float (*Ktp)[FP] = p ? Kt1 : Kt0;
        float (*Vsp)[FP] = p ? Vs1 : Vs0;

        // scores S = Q K^T
        float s[4][4];
#pragma unroll
        for (int i = 0; i < 4; i++)
#pragma unroll
            for (int j = 0; j < 4; j++) s[i][j] = 0.f;
#pragma unroll 8
        for (int e = 0; e < 64; e++) {
            float4 qv = *(float4*)&Qt[e][r0];
            float4 kv = *(float4*)&Ktp[e][c0];
            float ra[4] = {qv.x, qv.y, qv.z, qv.w};
            float rb[4] = {kv.x, kv.y, kv.z, kv.w};
#pragma unroll
            for (int i = 0; i < 4; i++)
#pragma unroll
                for (int j = 0; j < 4; j++) s[i][j] += ra[i] * rb[j];
        }

        if (kb == qb) {
#pragma unroll
            for (int i = 0; i < 4; i++)
#pragma unroll
                for (int j = 0; j < 4; j++)
                    if (c0 + j > r0 + i) s[i][j] = -INFINITY;
        }

        // online softmax
#pragma unroll
        for (int i = 0; i < 4; i++) {
            float mrow = fmaxf(fmaxf(s[i][0], s[i][1]), fmaxf(s[i][2], s[i][3]));
#pragma unroll
            for (int off = 8; off > 0; off >>= 1)
                mrow = fmaxf(mrow, __shfl_xor_sync(0xffffffffu, mrow, off, 16));
            float m_new = fmaxf(m_i[i], mrow);
            float alpha = __expf(m_i[i] - m_new);
            float rsum = 0.f;
#pragma unroll
            for (int j = 0; j < 4; j++) {
                float pj = __expf(s[i][j] - m_new);
                s[i][j] = pj;
                rsum += pj;
            }
#pragma unroll
            for (int off = 8; off > 0; off >>= 1)
                rsum += __shfl_xor_sync(0xffffffffu, rsum, off, 16);
            l_i[i] = l_i[i] * alpha + rsum;
            m_i[i] = m_new;
#pragma unroll
            for (int j = 0; j < 4; j++) acc[i][j] *= alpha;
        }

        __syncthreads();   // prev PV done with Pt; stage p^1 free

        // stage P (transposed); park next K/V tile in stage p^1
#pragma unroll
        for (int i = 0; i < 4; i++)
#pragma unroll
            for (int j = 0; j < 4; j++) Pt[c0 + j][r0 + i] = s[i][j];

        if (more) {
            float (*Ktn)[FP] = p ? Kt0 : Kt1;
            float (*Vsn)[FP] = p ? Vs0 : Vs1;
#pragma unroll
            for (int i = 0; i < 4; i++) {
                int idx4 = tid + i * 256;
                int c  = idx4 >> 4;
                int e4 = (idx4 & 15) * 4;
                Ktn[e4 + 0][c] = rk[i].x;
                Ktn[e4 + 1][c] = rk[i].y;
                Ktn[e4 + 2][c] = rk[i].z;
                Ktn[e4 + 3][c] = rk[i].w;
                *(float4*)&Vsn[c][e4] = rv[i];
            }
        }
        __syncthreads();

        // O += P @ V
#pragma unroll 8
        for (int c = 0; c < 64; c++) {
            float4 pv = *(float4*)&Pt[c][r0];
            float4 vv = *(float4*)&Vsp[c][c0];
            float ra[4] = {pv.x, pv.y, pv.z, pv.w};
            float rb[4] = {vv.x, vv.y, vv.z, vv.w};
#pragma unroll
            for (int i = 0; i < 4; i++)
#pragma unroll
                for (int j = 0; j < 4; j++) acc[i][j] += ra[i] * rb[j];
        }
        p ^= 1;
    }

    // write O in [b,s,d] layout
#pragma unroll
    for (int i = 0; i < 4; i++) {
        float inv_l = 1.f / l_i[i];
        int srow = qb * 64 + r0 + i;
        float4 o;
        o.x = acc[i][0] * inv_l;
        o.y = acc[i][1] * inv_l;
        o.z = acc[i][2] * inv_l;
        o.w = acc[i][3] * inv_l;
        *(float4*)&g_attn[(size_t)(b * S_ + srow) * D_ + h * HS_ + c0] = o;
    }
}

// ---------------- launch ------------------------------------------------------
extern "C" void kernel_launch(void* const* d_in, const int* in_sizes, int n_in,
                              void* d_out, int out_size) {
    const float* x  = (const float*)d_in[0];
    const float* Wq = (const float*)d_in[1];
    const float* Wk = (const float*)d_in[2];
    const float* Wv = (const float*)d_in[3];
    const float* Wo = (const float*)d_in[4];
    const float* bo = (const float*)d_in[5];
    float* out = (float*)d_out;

    {
        int total = D_ * N3_;
        repack_w<<<(total + 255) / 256, 256>>>(Wq, Wk, Wv);
    }
    {
        dim3 grid(N3_ / 128, M_ / 128);
        gemm_qkv<<<grid, 256>>>(x);
    }
    {
        int smem = 6 * FT * sizeof(float);   // 104448 B
        static bool attr_set = false;
        if (!attr_set) {
            cudaFuncSetAttribute(flash_attn,
                                 cudaFuncAttributeMaxDynamicSharedMemorySize, smem);
            attr_set = true;
        }
        dim3 grid(S_ / 64, B_ * H_);
        flash_attn<<<grid, 256, smem>>>();
    }
    {
        dim3 grid(D_ / 128, M_ / 128);
        gemm_out<<<grid, 256>>>(Wo, bo, out);
    }
}